// round 8
// baseline (speedup 1.0000x reference)
#include <cuda_runtime.h>

#define K          84
#define CHUNKS     21          // K/4 (16B chunks per row)
#define NPROTO     10
#define HALFP      5           // protos per warp-half
#define THREADS    256         // 8 warps: 0-3 -> protos 0-4, 4-7 -> protos 5-9
#define STAGE_ROWS 128
#define STAGE_FLOATS (STAGE_ROWS * K)        // 10752
#define STAGE_VEC4   (STAGE_FLOATS / 4)      // 2688
#define LOADERS    128                        // threads issuing cp.async
#define COPIES_PER_LOADER (STAGE_VEC4 / LOADERS)  // 21

// dynamic smem per CTA:  2*43008 + 3360 + 64 = 89440 B  -> 2 CTAs/SM, 16 warps/SM
#define SMEM_BYTES (2 * STAGE_FLOATS * 4 + CHUNKS * NPROTO * 16 + 64)

__device__ __forceinline__ void ffma2(unsigned long long &d,
                                      unsigned long long a,
                                      unsigned long long b) {
    asm("fma.rn.f32x2 %0, %1, %2, %0;" : "+l"(d) : "l"(a), "l"(b));
}
__device__ __forceinline__ float f2lo(unsigned long long v) {
    return __int_as_float((unsigned)(v & 0xffffffffULL));
}
__device__ __forceinline__ float f2hi(unsigned long long v) {
    return __int_as_float((unsigned)(v >> 32));
}
__device__ __forceinline__ void cp_async16(unsigned smem_addr, const void* gptr) {
    asm volatile("cp.async.cg.shared.global [%0], [%1], 16;\n"
                 :: "r"(smem_addr), "l"(gptr));
}
__device__ __forceinline__ void cp_commit() {
    asm volatile("cp.async.commit_group;\n" ::: "memory");
}
__device__ __forceinline__ void cp_wait1() {
    asm volatile("cp.async.wait_group 1;\n" ::: "memory");
}

__global__ void __launch_bounds__(THREADS, 2)
rbf_kernel(const float* __restrict__ x,
           const float* __restrict__ weight,
           float* __restrict__ out,
           int nrows) {
    extern __shared__ __align__(16) float smem[];
    float* s_buf0 = smem;                                 // [STAGE_FLOATS]
    float* s_buf1 = smem + STAGE_FLOATS;                  // [STAGE_FLOATS]
    ulonglong2* s_w = (ulonglong2*)(smem + 2 * STAGE_FLOATS); // [CHUNKS*NPROTO]
    float* s_w2 = (float*)(s_w + CHUNKS * NPROTO);        // [16]

    const int t    = threadIdx.x;
    const int tr   = t & (STAGE_ROWS - 1);   // row within stage (0..127)
    const int half = t >> 7;                 // 0: protos 0-4, 1: protos 5-9
    const int k0   = half * HALFP;

    // ---- build weight blocks: s_w[c*10+k] = chunk c of proto k ----
    for (int i = t; i < CHUNKS * NPROTO; i += THREADS) {
        int c = i / NPROTO;
        int k = i - c * NPROTO;
        const float4 v = *(const float4*)(weight + k * K + 4 * c);
        ulonglong2 u;
        u.x = ((unsigned long long)__float_as_uint(v.y) << 32) | __float_as_uint(v.x);
        u.y = ((unsigned long long)__float_as_uint(v.w) << 32) | __float_as_uint(v.z);
        s_w[i] = u;
    }
    if (t < NPROTO) {
        float s = 0.f;
        #pragma unroll
        for (int j = 0; j < K; j++) { float w = weight[t * K + j]; s += w * w; }
        s_w2[t] = s;
    }

    const int nstages = (nrows + STAGE_ROWS - 1) / STAGE_ROWS;  // 4096
    const int step = gridDim.x;
    int count = 0;
    for (long long s = blockIdx.x; s < nstages; s += step) count++;

    unsigned buf_addr[2];
    buf_addr[0] = (unsigned)__cvta_generic_to_shared(s_buf0);
    buf_addr[1] = (unsigned)__cvta_generic_to_shared(s_buf1);
    const float* bufs[2] = { s_buf0, s_buf1 };

    // only threads 0..127 issue copies; everyone commits (uniform group count)
    auto issue_stage = [&](int j) {
        if (t < LOADERS) {
            long long stage = (long long)blockIdx.x + (long long)j * step;
            const float4* gx = (const float4*)x + stage * STAGE_VEC4;
            unsigned dst = buf_addr[j & 1] + t * 16;
            const float4* src = gx + t;
            long long remaining4 = ((long long)nrows * K) / 4 - stage * STAGE_VEC4;
            if (remaining4 >= STAGE_VEC4) {
                #pragma unroll
                for (int i = 0; i < COPIES_PER_LOADER; i++)
                    cp_async16(dst + i * LOADERS * 16, src + i * LOADERS);
            } else {
                #pragma unroll
                for (int i = 0; i < COPIES_PER_LOADER; i++)
                    if (i * LOADERS + t < remaining4)
                        cp_async16(dst + i * LOADERS * 16, src + i * LOADERS);
            }
        }
        cp_commit();
    };

    // ---- pipeline prologue ----
    if (count > 0) issue_stage(0);
    else cp_commit();
    if (count > 1) issue_stage(1);
    else cp_commit();

    __syncthreads();   // covers s_w / s_w2 init

    for (int j = 0; j < count; j++) {
        cp_wait1();
        __syncthreads();   // publish buffer j%2 to all 8 warps

        const long long stage = (long long)blockIdx.x + (long long)j * step;
        const float* sx = bufs[j & 1];

        const ulonglong2* rowA = (const ulonglong2*)(sx + tr * K);

        unsigned long long acc[HALFP];
        unsigned long long x2a = 0ULL;
        #pragma unroll
        for (int k = 0; k < HALFP; k++) acc[k] = 0ULL;

        #pragma unroll
        for (int c = 0; c < CHUNKS; c++) {
            ulonglong2 va = rowA[c];
            ffma2(x2a, va.x, va.x);
            ffma2(x2a, va.y, va.y);
            #pragma unroll
            for (int k = 0; k < HALFP; k++) {
                ulonglong2 wv = s_w[c * NPROTO + k0 + k];
                ffma2(acc[k], va.x, wv.x);
                ffma2(acc[k], va.y, wv.y);
            }
        }

        float x2A = f2lo(x2a) + f2hi(x2a);

        float res[HALFP];
        #pragma unroll
        for (int k = 0; k < HALFP; k++)
            res[k] = fmaf(-2.f, f2lo(acc[k]) + f2hi(acc[k]), x2A + s_w2[k0 + k]);

        const long long rA = stage * STAGE_ROWS + tr;
        if (rA < nrows) {
            float* o = out + rA * NPROTO;
            if (half == 0) {
                // cols 0-4: float2@0, float2@2, float@4  (row base 8B-aligned)
                *(float2*)(o + 0) = make_float2(res[0], res[1]);
                *(float2*)(o + 2) = make_float2(res[2], res[3]);
                o[4] = res[4];
            } else {
                // cols 5-9: float@5, float2@6, float2@8
                o[5] = res[0];
                *(float2*)(o + 6) = make_float2(res[1], res[2]);
                *(float2*)(o + 8) = make_float2(res[3], res[4]);
            }
        }

        __syncthreads();                 // buffer j%2 fully consumed
        if (j + 2 < count) issue_stage(j + 2);
        else cp_commit();
    }
}

extern "C" void kernel_launch(void* const* d_in, const int* in_sizes, int n_in,
                              void* d_out, int out_size) {
    const float* x = (const float*)d_in[0];
    const float* w = (const float*)d_in[1];
    float* out = (float*)d_out;

    const int nrows = in_sizes[0] / K;   // 524288

    static int nsm = 0;
    if (nsm == 0) {
        cudaFuncSetAttribute(rbf_kernel,
                             cudaFuncAttributeMaxDynamicSharedMemorySize,
                             SMEM_BYTES);
        cudaDeviceGetAttribute(&nsm, cudaDevAttrMultiProcessorCount, 0);
        if (nsm <= 0) nsm = 148;
    }

    // 2 CTAs/SM x 8 warps: proto-split doubles warps per byte of smem
    rbf_kernel<<<2 * nsm, THREADS, SMEM_BYTES>>>(x, w, out, nrows);
}

// round 9
// speedup vs baseline: 1.2058x; 1.2058x over previous
#include <cuda_runtime.h>

#define K          84
#define CHUNKS     21          // K/4 (16B chunks per row)
#define NPROTO     10
#define THREADS    128
#define STAGE_ROWS 128
#define STAGE_FLOATS (STAGE_ROWS * K)        // 10752
#define STAGE_BYTES  (STAGE_FLOATS * 4)      // 43008

// dynamic smem per CTA:
//   buf[2][STAGE_FLOATS]   2*43008 B
//   wblk[210] ulonglong2   3360 B
//   w2[16] floats          64 B
//   mbar[2] u64            16 B (+pad)
#define SMEM_BYTES (2 * STAGE_BYTES + CHUNKS * NPROTO * 16 + 64 + 32)

__device__ __forceinline__ void ffma2(unsigned long long &d,
                                      unsigned long long a,
                                      unsigned long long b) {
    asm("fma.rn.f32x2 %0, %1, %2, %0;" : "+l"(d) : "l"(a), "l"(b));
}
__device__ __forceinline__ float f2lo(unsigned long long v) {
    return __int_as_float((unsigned)(v & 0xffffffffULL));
}
__device__ __forceinline__ float f2hi(unsigned long long v) {
    return __int_as_float((unsigned)(v >> 32));
}

__device__ __forceinline__ void mbar_init(unsigned mbar, unsigned count) {
    asm volatile("mbarrier.init.shared.b64 [%0], %1;" :: "r"(mbar), "r"(count) : "memory");
}
__device__ __forceinline__ void mbar_expect_tx(unsigned mbar, unsigned bytes) {
    asm volatile("mbarrier.arrive.expect_tx.shared.b64 _, [%0], %1;"
                 :: "r"(mbar), "r"(bytes) : "memory");
}
__device__ __forceinline__ void mbar_wait(unsigned mbar, unsigned parity) {
    unsigned done;
    asm volatile(
        "{\n\t"
        ".reg .pred p;\n\t"
        "mbarrier.try_wait.parity.acquire.cta.shared::cta.b64 p, [%1], %2;\n\t"
        "selp.b32 %0, 1, 0, p;\n\t"
        "}" : "=r"(done) : "r"(mbar), "r"(parity) : "memory");
    if (!done) {
        asm volatile(
            "{\n\t"
            ".reg .pred P1;\n\t"
            "WAIT_LOOP_%=:\n\t"
            "mbarrier.try_wait.parity.acquire.cta.shared::cta.b64 P1, [%0], %1, 0x989680;\n\t"
            "@P1 bra.uni WAIT_DONE_%=;\n\t"
            "bra.uni WAIT_LOOP_%=;\n\t"
            "WAIT_DONE_%=:\n\t"
            "}" :: "r"(mbar), "r"(parity) : "memory");
    }
}
// 1D bulk copy global -> shared::cta with mbarrier completion (TMA path)
__device__ __forceinline__ void bulk_g2s(unsigned dst_smem, const void* src,
                                         unsigned bytes, unsigned mbar) {
    asm volatile(
        "cp.async.bulk.shared::cta.global.mbarrier::complete_tx::bytes "
        "[%0], [%1], %2, [%3];"
        :: "r"(dst_smem), "l"(src), "r"(bytes), "r"(mbar) : "memory");
}

__global__ void __launch_bounds__(THREADS, 2)
rbf_kernel(const float* __restrict__ x,
           const float* __restrict__ weight,
           float* __restrict__ out,
           int nrows) {
    extern __shared__ __align__(16) float smem[];
    float* s_buf0 = smem;                                 // [STAGE_FLOATS]
    float* s_buf1 = smem + STAGE_FLOATS;                  // [STAGE_FLOATS]
    ulonglong2* s_w = (ulonglong2*)(smem + 2 * STAGE_FLOATS); // [210]
    float* s_w2 = (float*)(s_w + CHUNKS * NPROTO);        // [16]
    unsigned long long* s_mbar = (unsigned long long*)(s_w2 + 16); // [2]

    const int t = threadIdx.x;

    // ---- weight blocks: s_w[c*10+k] = chunk c of proto k ----
    for (int i = t; i < CHUNKS * NPROTO; i += THREADS) {
        int c = i / NPROTO;
        int k = i - c * NPROTO;
        const float4 v = *(const float4*)(weight + k * K + 4 * c);
        ulonglong2 u;
        u.x = ((unsigned long long)__float_as_uint(v.y) << 32) | __float_as_uint(v.x);
        u.y = ((unsigned long long)__float_as_uint(v.w) << 32) | __float_as_uint(v.z);
        s_w[i] = u;
    }
    if (t < NPROTO) {
        float s = 0.f;
        #pragma unroll
        for (int j = 0; j < K; j++) { float w = weight[t * K + j]; s += w * w; }
        s_w2[t] = s;
    }

    const unsigned mbar0 = (unsigned)__cvta_generic_to_shared(&s_mbar[0]);
    const unsigned mbar1 = (unsigned)__cvta_generic_to_shared(&s_mbar[1]);
    if (t == 0) { mbar_init(mbar0, 1); mbar_init(mbar1, 1); }

    unsigned buf_addr[2];
    buf_addr[0] = (unsigned)__cvta_generic_to_shared(s_buf0);
    buf_addr[1] = (unsigned)__cvta_generic_to_shared(s_buf1);
    const float* bufs[2] = { s_buf0, s_buf1 };
    const unsigned mbars[2] = { mbar0, mbar1 };

    const int nstages = (nrows + STAGE_ROWS - 1) / STAGE_ROWS;  // 4096
    const int step = gridDim.x;
    int count = 0;
    for (long long s = blockIdx.x; s < nstages; s += step) count++;

    __syncthreads();   // weights + mbarrier init visible to all

    // tid0 issues one bulk copy per stage
    auto issue_stage = [&](int j) {
        if (t == 0) {
            long long stage = (long long)blockIdx.x + (long long)j * step;
            long long row0 = stage * STAGE_ROWS;
            long long rem_rows = (long long)nrows - row0;
            unsigned bytes = (rem_rows >= STAGE_ROWS)
                           ? STAGE_BYTES
                           : (unsigned)(rem_rows * K * 4);
            mbar_expect_tx(mbars[j & 1], bytes);
            bulk_g2s(buf_addr[j & 1], x + row0 * K, bytes, mbars[j & 1]);
        }
    };

    if (count > 0) issue_stage(0);
    if (count > 1) issue_stage(1);

    for (int j = 0; j < count; j++) {
        // buffer (j&1) is on its ((j>>1)&1)-th fill: wait that parity
        mbar_wait(mbars[j & 1], (unsigned)((j >> 1) & 1));

        const long long stage = (long long)blockIdx.x + (long long)j * step;
        const float* sx = bufs[j & 1];

        const ulonglong2* rowA = (const ulonglong2*)(sx + t * K);

        unsigned long long acc[NPROTO];
        unsigned long long x2a = 0ULL;
        #pragma unroll
        for (int k = 0; k < NPROTO; k++) acc[k] = 0ULL;

        #pragma unroll
        for (int c = 0; c < CHUNKS; c++) {
            ulonglong2 va = rowA[c];
            ffma2(x2a, va.x, va.x);
            ffma2(x2a, va.y, va.y);
            #pragma unroll
            for (int k = 0; k < NPROTO; k++) {
                ulonglong2 wv = s_w[c * NPROTO + k];
                ffma2(acc[k], va.x, wv.x);
                ffma2(acc[k], va.y, wv.y);
            }
        }

        float x2A = f2lo(x2a) + f2hi(x2a);

        const long long rA = stage * STAGE_ROWS + t;
        if (rA < nrows) {
            float2* o = (float2*)(out + rA * NPROTO);
            #pragma unroll
            for (int k = 0; k < 5; k++) {
                float w2a = s_w2[2 * k], w2b = s_w2[2 * k + 1];
                o[k] = make_float2(
                    fmaf(-2.f, f2lo(acc[2 * k])     + f2hi(acc[2 * k]),     x2A + w2a),
                    fmaf(-2.f, f2lo(acc[2 * k + 1]) + f2hi(acc[2 * k + 1]), x2A + w2b));
            }
        }

        __syncthreads();                 // all lanes done reading buffer j&1
        if (j + 2 < count) issue_stage(j + 2);
    }
}

extern "C" void kernel_launch(void* const* d_in, const int* in_sizes, int n_in,
                              void* d_out, int out_size) {
    const float* x = (const float*)d_in[0];
    const float* w = (const float*)d_in[1];
    float* out = (float*)d_out;

    const int nrows = in_sizes[0] / K;   // 524288

    static int nsm = 0;
    if (nsm == 0) {
        cudaFuncSetAttribute(rbf_kernel,
                             cudaFuncAttributeMaxDynamicSharedMemorySize,
                             SMEM_BYTES);
        cudaDeviceGetAttribute(&nsm, cudaDevAttrMultiProcessorCount, 0);
        if (nsm <= 0) nsm = 148;
    }

    // 2 CTAs/SM; stage fill via TMA bulk copy (off the L1tex port)
    rbf_kernel<<<2 * nsm, THREADS, SMEM_BYTES>>>(x, w, out, nrows);
}